// round 12
// baseline (speedup 1.0000x reference)
#include <cuda_runtime.h>
#include <cstdint>
#include <math.h>

typedef unsigned long long ull;

#define NB 32
#define NS 512
#define NE 300
#define NHH 256
#define NT 12
#define NGATE 1024
#define TAG_START 10
#define TAG_STOP 11
#define FNEG (-10000.0f)

// ---------------- scratch (static device arrays; no allocation) ----------------
static __device__ float g_gates[2u * NS * NB * NGATE];   // [dir][m=s*32+b][1024]
static __device__ float g_h[2u * NS * NB * NHH];         // [dir][s][b][256]
static __device__ float g_feat[(size_t)NB * NS * NT];    // [b][s][12]

__device__ __forceinline__ float sigf(float x) { return 1.f / (1.f + __expf(-x)); }

__device__ __forceinline__ ull pack2(float lo, float hi) {
    ull r; asm("mov.b64 %0, {%1, %2};" : "=l"(r) : "f"(lo), "f"(hi)); return r;
}
__device__ __forceinline__ float2 unpack2(ull v) {
    float2 f; asm("mov.b64 {%0, %1}, %2;" : "=f"(f.x), "=f"(f.y) : "l"(v)); return f;
}
__device__ __forceinline__ void ffma2(ull& d, ull a, ull b) {
    asm("fma.rn.f32x2 %0, %1, %2, %0;" : "+l"(d) : "l"(a), "l"(b));
}
__device__ __forceinline__ uint32_t smem_u32(const void* p) {
    uint32_t a;
    asm("{ .reg .u64 t; cvta.to.shared.u64 t, %1; cvt.u32.u64 %0, t; }" : "=r"(a) : "l"(p));
    return a;
}
__device__ __forceinline__ uint32_t mapa_rank(uint32_t addr, int rank) {
    uint32_t r;
    asm("mapa.shared::cluster.u32 %0, %1, %2;" : "=r"(r) : "r"(addr), "r"(rank));
    return r;
}
__device__ __forceinline__ void mbar_wait_cluster(uint32_t mbar, uint32_t parity) {
    uint32_t done;
    do {
        asm volatile(
            "{ .reg .pred p;\n\t"
            "mbarrier.try_wait.parity.acquire.cluster.shared::cta.b64 p, [%1], %2;\n\t"
            "selp.b32 %0, 1, 0, p; }"
            : "=r"(done) : "r"(mbar), "r"(parity) : "memory");
    } while (!done);
}

__global__ void nop_kernel() {}

// ---------------- Phase A: embedding gather + input GEMM (f32x2) ----------------
// BM=128, BN=64, BK=20. 256 threads, 8x4 microtile, k-paired accumulators. (R6 version)
__global__ void __launch_bounds__(256)
input_gemm_kernel(const int* __restrict__ inputs,
                  const float* __restrict__ embed,
                  const float* __restrict__ wih_f,
                  const float* __restrict__ bih_f,
                  const float* __restrict__ bhh_f,
                  const float* __restrict__ wih_b,
                  const float* __restrict__ bih_b,
                  const float* __restrict__ bhh_b) {
    const int dir = blockIdx.z;
    const float* __restrict__ wih = dir ? wih_b : wih_f;
    const float* __restrict__ bih = dir ? bih_b : bih_f;
    const float* __restrict__ bhh = dir ? bhh_b : bhh_f;
    const int n0 = blockIdx.x * 64;
    const int m0 = blockIdx.y * 128;

    __shared__ int    tok_s[128];
    __shared__ float2 A_s[10 * 128];
    __shared__ float2 W_s[10 * 64];

    const int tid = threadIdx.x;
    if (tid < 128) {
        const int m = m0 + tid;
        tok_s[tid] = inputs[(m & 31) * NS + (m >> 5)];
    }
    const int tn = tid & 15;
    const int tm = tid >> 4;

    ull acc[8][4];
#pragma unroll
    for (int i = 0; i < 8; i++)
#pragma unroll
        for (int j = 0; j < 4; j++) acc[i][j] = 0ull;

    __syncthreads();
    for (int kt = 0; kt < 15; kt++) {
        const int k0 = kt * 20;
        __syncthreads();
        for (int u = tid; u < 960; u += 256) {
            if (u < 640) {
                const int row = u / 5, c4 = u % 5;
                const float4 v = *(const float4*)(embed + (size_t)tok_s[row] * NE + k0 + c4 * 4);
                A_s[(c4 * 2) * 128 + row]     = make_float2(v.x, v.y);
                A_s[(c4 * 2 + 1) * 128 + row] = make_float2(v.z, v.w);
            } else {
                const int idx = u - 640;
                const int n = idx / 5, c4 = idx % 5;
                const float4 v = *(const float4*)(wih + (size_t)(n0 + n) * NE + k0 + c4 * 4);
                W_s[(c4 * 2) * 64 + n]     = make_float2(v.x, v.y);
                W_s[(c4 * 2 + 1) * 64 + n] = make_float2(v.z, v.w);
            }
        }
        __syncthreads();
#pragma unroll
        for (int kp = 0; kp < 10; kp++) {
            const ulonglong2* ap = (const ulonglong2*)(A_s + kp * 128 + tm * 8);
            const ulonglong2* wp = (const ulonglong2*)(W_s + kp * 64 + tn * 4);
            const ulonglong2 a0 = ap[0], a1 = ap[1], a2 = ap[2], a3 = ap[3];
            const ulonglong2 w0 = wp[0], w1 = wp[1];
            const ull a[8] = {a0.x, a0.y, a1.x, a1.y, a2.x, a2.y, a3.x, a3.y};
            const ull w[4] = {w0.x, w0.y, w1.x, w1.y};
#pragma unroll
            for (int i = 0; i < 8; i++)
#pragma unroll
                for (int j = 0; j < 4; j++) ffma2(acc[i][j], a[i], w[j]);
        }
    }

    const int ncol = n0 + tn * 4;
    const float4 b1 = *(const float4*)(bih + ncol);
    const float4 b2 = *(const float4*)(bhh + ncol);
    const float bx = b1.x + b2.x, by = b1.y + b2.y, bz = b1.z + b2.z, bw = b1.w + b2.w;
#pragma unroll
    for (int i = 0; i < 8; i++) {
        const int m = m0 + tm * 8 + i;
        const float2 s0 = unpack2(acc[i][0]);
        const float2 s1 = unpack2(acc[i][1]);
        const float2 s2 = unpack2(acc[i][2]);
        const float2 s3 = unpack2(acc[i][3]);
        const float4 o = make_float4(s0.x + s0.y + bx, s1.x + s1.y + by,
                                     s2.x + s2.y + bz, s3.x + s3.y + bw);
        *(float4*)(g_gates + ((size_t)dir * (NS * NB) + m) * NGATE + ncol) = o;
    }
}

// ---------------- Phase B: cluster-local LSTM, mbarrier + vectorized DSMEM push ----------------
// 128 CTAs = 16 clusters of 8. Cluster = (dir, batch-group of 4). CTA rank owns 32 units.
// Exchange: local h staging -> 256 x st.shared::cluster.v4 -> syncthreads -> 8 remote
// mbarrier.arrive.release.cluster. Consumers try_wait.acquire.cluster on LOCAL mbarrier.
#define HPADF 260
#define HBUF_B 4160      // 4*260*4 bytes per buffer
#define OFF_H    131072
#define OFF_PS   (OFF_H + 2 * HBUF_B)          // 139392
#define OFF_HMY  (OFF_PS + 16384)              // 155776
#define OFF_MBAR (OFF_HMY + 512)               // 156288
#define LSTM_SMEM (OFF_MBAR + 32)              // 156320
__global__ void __launch_bounds__(256, 1) __cluster_dims__(8, 1, 1)
lstm_rec_kernel(const float* __restrict__ whh_f,
                const float* __restrict__ whh_b) {
    extern __shared__ char smraw[];
    ull*   w2_s = (ull*)smraw;                       // [k=256][rp=64]
    float* h0   = (float*)(smraw + OFF_H);           // [2][4][260]
    ull*   p_s  = (ull*)(smraw + OFF_PS);            // [ks=8][b=4][rp=64]
    float* h_my = (float*)(smraw + OFF_HMY);         // [4][32]

    const int tid = threadIdx.x;
    const int cid = blockIdx.x >> 3;
    const int rank = blockIdx.x & 7;
    const int dir = cid >> 3;
    const int bgr = cid & 7;
    const float* __restrict__ whh = dir ? whh_b : whh_f;
    const uint32_t smbase = smem_u32(smraw);
    const uint32_t mbar0 = smbase + OFF_MBAR;

    if (tid == 0) {
        asm volatile("mbarrier.init.shared.b64 [%0], 8;" :: "r"(mbar0) : "memory");
        asm volatile("mbarrier.init.shared.b64 [%0], 8;" :: "r"(mbar0 + 8) : "memory");
    }

    // weights: w2_s[k*64 + rp] = pack(whh[row(2rp)][k], whh[row(2rp+1)][k]); r = u*4+g
    for (int idx = tid; idx < 16384; idx += 256) {
        const int rp = idx >> 8, k = idx & 255;
        const int r0 = rp * 2;
        const int u = r0 >> 2, g0 = r0 & 3;
        const float w0 = whh[(size_t)(g0 * 256 + rank * 32 + u) * NHH + k];
        const float w1 = whh[(size_t)((g0 + 1) * 256 + rank * 32 + u) * NHH + k];
        w2_s[k * 64 + rp] = pack2(w0, w1);
    }
    __syncthreads();
    asm volatile("barrier.cluster.arrive.aligned;" ::: "memory");
    asm volatile("barrier.cluster.wait.aligned;" ::: "memory");

    const int lane = tid & 31;
    const int ks = tid >> 5;                   // warp = k-slice (32 k)
    const int bL = lane >> 3, rq = lane & 7;   // compute roles
    const int bE = tid >> 5, uE = tid & 31;    // epilogue roles (tid<128)
    const int bglobal = bgr * 4 + bE;
    const int uglobal = rank * 32 + uE;
    // exchange role: one float4 per thread
    const int xr = tid & 7, xf = tid >> 3;          // dest rank, float4 id 0..31
    const int xb = xf >> 3, xq = xf & 7;            // batch, quarter
    const uint32_t xsrc_off = (uint32_t)(OFF_HMY + (xb * 32 + xq * 4) * 4);
    const uint32_t xdst_off = (uint32_t)(OFF_H + (xb * HPADF + rank * 32 + xq * 4) * 4);

    float c_reg = 0.f;
    const size_t hb_dir = (size_t)dir * NS * NB * NHH;
    const float* const gdir = g_gates + (size_t)dir * (NS * NB * NGATE) + uglobal;

    float n_i = 0.f, n_f = 0.f, n_g = 0.f, n_o = 0.f;
    if (tid < 128) {
        const int s0 = dir ? (NS - 1) : 0;
        const float* gp = gdir + ((size_t)s0 * NB + bglobal) * NGATE;
        n_i = __ldcg(gp); n_f = __ldcg(gp + 256); n_g = __ldcg(gp + 512); n_o = __ldcg(gp + 768);
    }

    for (int t = 0; t < NS; t++) {
        const int s = dir ? (NS - 1 - t) : t;
        float a_i = n_i, a_f = n_f, a_g = n_g, a_o = n_o;
        if (tid < 128 && t + 1 < NS) {
            const int sn = dir ? (s - 1) : (s + 1);
            const float* gp = gdir + ((size_t)sn * NB + bglobal) * NGATE;
            n_i = __ldcg(gp); n_f = __ldcg(gp + 256); n_g = __ldcg(gp + 512); n_o = __ldcg(gp + 768);
        }

        if (t > 0) {
            // wait for step t-1's h (buffer (t-1)&1), phase ((t-1)>>1)&1
            mbar_wait_cluster(mbar0 + ((t - 1) & 1) * 8, (uint32_t)(((t - 1) >> 1) & 1));
            const int q = (t - 1) & 1;
            const float* hq = h0 + q * (HPADF * 4) + bL * HPADF;

            ull acc[8];
#pragma unroll
            for (int j = 0; j < 8; j++) acc[j] = 0ull;
            const int kbase = ks * 32;
#pragma unroll 4
            for (int kk = 0; kk < 32; kk++) {
                const int k = kbase + kk;
                const float h = hq[k];
                const ull hh = pack2(h, h);
                const ulonglong2* wrow = (const ulonglong2*)(w2_s + k * 64 + rq * 8);
#pragma unroll
                for (int j2 = 0; j2 < 4; j2++) {
                    const ulonglong2 w = wrow[j2];
                    ffma2(acc[j2 * 2],     hh, w.x);
                    ffma2(acc[j2 * 2 + 1], hh, w.y);
                }
            }
            ulonglong2* pp = (ulonglong2*)(p_s + (ks * 4 + bL) * 64 + rq * 8);
#pragma unroll
            for (int j2 = 0; j2 < 4; j2++)
                pp[j2] = make_ulonglong2(acc[j2 * 2], acc[j2 * 2 + 1]);
        }
        __syncthreads();

        if (tid < 128) {
            if (t > 0) {
#pragma unroll
                for (int kq = 0; kq < 8; kq++) {
                    const ulonglong2 v = *(const ulonglong2*)(p_s + (kq * 4 + bE) * 64 + 2 * uE);
                    const float2 vif = unpack2(v.x);
                    const float2 vgo = unpack2(v.y);
                    a_i += vif.x; a_f += vif.y;
                    a_g += vgo.x; a_o += vgo.y;
                }
            }
            const float ig = sigf(a_i), fg = sigf(a_f), og = sigf(a_o);
            const float tg = 2.f * sigf(2.f * a_g) - 1.f;             // tanh
            const float cn = fg * c_reg + ig * tg;
            const float hn = og * (2.f * sigf(2.f * cn) - 1.f);
            c_reg = cn;
            __stcg(g_h + hb_dir + ((size_t)s * NB + bglobal) * NHH + uglobal, hn);
            h_my[bE * 32 + uE] = hn;
        }
        __syncthreads();

        if (t + 1 < NS) {
            // vectorized DSMEM push: one float4 per thread to rank xr's buffer t&1
            const float4 v = *(const float4*)((const char*)smraw + xsrc_off);
            const uint32_t dst = mapa_rank(smbase + xdst_off + (uint32_t)((t & 1) * HBUF_B), xr);
            asm volatile("st.shared::cluster.v4.f32 [%0], {%1, %2, %3, %4};"
                         :: "r"(dst), "f"(v.x), "f"(v.y), "f"(v.z), "f"(v.w) : "memory");
            __syncthreads();
            if (tid < 8) {
                const uint32_t rm = mapa_rank(mbar0 + (t & 1) * 8, tid);
                asm volatile("mbarrier.arrive.release.cluster.shared::cluster.b64 _, [%0];"
                             :: "r"(rm) : "memory");
            }
        }
    }
    // all remote ops of step NS-2 were consumed by every CTA's wait at NS-1; none at NS-1.
}

// ---------------- Phase C1: feats = hs @ fc_w^T + fc_b ----------------
__global__ void feats_kernel(const float* __restrict__ fc_w,
                             const float* __restrict__ fc_b) {
    __shared__ float fcw_s[NT * 512];
    __shared__ float fcb_s[NT];
    const int s = blockIdx.x;
    const int tid = threadIdx.x;
    for (int i = tid; i < NT * 512; i += 256) fcw_s[i] = fc_w[i];
    if (tid < NT) fcb_s[tid] = fc_b[tid];
    __syncthreads();

    const int w = tid >> 5, lane = tid & 31;
#pragma unroll
    for (int rep = 0; rep < 4; rep++) {
        const int b = w + rep * 8;
        const float4* hf = (const float4*)(g_h + ((size_t)s * NB + b) * NHH);
        const float4* hb = (const float4*)(g_h + (size_t)NS * NB * NHH + ((size_t)s * NB + b) * NHH);
        const float4 v0 = __ldcg(hf + lane);
        const float4 v1 = __ldcg(hf + lane + 32);
        const float4 v2 = __ldcg(hb + lane);
        const float4 v3 = __ldcg(hb + lane + 32);
#pragma unroll
        for (int tt = 0; tt < NT; tt++) {
            const float4* wr = (const float4*)(fcw_s + tt * 512);
            const float4 w0 = wr[lane];
            const float4 w1 = wr[lane + 32];
            const float4 w2 = wr[lane + 64];
            const float4 w3 = wr[lane + 96];
            float p = v0.x * w0.x + v0.y * w0.y + v0.z * w0.z + v0.w * w0.w
                    + v1.x * w1.x + v1.y * w1.y + v1.z * w1.z + v1.w * w1.w
                    + v2.x * w2.x + v2.y * w2.y + v2.z * w2.z + v2.w * w2.w
                    + v3.x * w3.x + v3.y * w3.y + v3.z * w3.z + v3.w * w3.w;
            p += __shfl_xor_sync(0xffffffffu, p, 16);
            p += __shfl_xor_sync(0xffffffffu, p, 8);
            p += __shfl_xor_sync(0xffffffffu, p, 4);
            p += __shfl_xor_sync(0xffffffffu, p, 2);
            p += __shfl_xor_sync(0xffffffffu, p, 1);
            if (lane == 0) g_feat[((size_t)b * NS + s) * NT + tt] = p + fcb_s[tt];
        }
    }
}

// ---------------- Phase C2: Viterbi, one warp per batch ----------------
__global__ void viterbi_kernel(const float* __restrict__ trans,
                               float* __restrict__ out, int out_size) {
    __shared__ float feat_s[NS * NT];
    __shared__ unsigned char bp_s[NS * NT];
    __shared__ float term_s[NT];
    const int b = blockIdx.x;
    const int lane = threadIdx.x;  // 32

    const float4* src = (const float4*)(g_feat + (size_t)b * NS * NT);
    float4* dst = (float4*)feat_s;
    for (int i = lane; i < (NS * NT) / 4; i += 32) dst[i] = __ldcg(src + i);

    const int tl = (lane < NT) ? lane : (NT - 1);
    float tr_reg[NT];
#pragma unroll
    for (int p = 0; p < NT; p++) tr_reg[p] = trans[p * NT + tl];
    const float tr_stop = trans[tl * NT + TAG_STOP];
    __syncwarp();

    float v = (lane == TAG_START) ? 0.f : FNEG;
    for (int s = 0; s < NS; s++) {
        float best = -3.0e38f;
        int bpi = 0;
#pragma unroll
        for (int p = 0; p < NT; p++) {
            const float sc = __shfl_sync(0xffffffffu, v, p) + tr_reg[p];
            if (sc > best) { best = sc; bpi = p; }
        }
        v = best + feat_s[s * NT + tl];
        if (lane < NT) bp_s[s * NT + lane] = (unsigned char)bpi;
    }
    if (lane < NT) term_s[lane] = v + tr_stop;
    __syncwarp();
    if (lane == 0) {
        float best = term_s[0];
        int last = 0;
#pragma unroll
        for (int tt = 1; tt < NT; tt++)
            if (term_s[tt] > best) { best = term_s[tt]; last = tt; }
        if (b < out_size) out[b] = best;
        const int base = NB + b * NS;
        if (base + NS - 1 < out_size) out[base + NS - 1] = (float)last;
        int tag = last;
        for (int s = NS - 1; s >= 0; s--) {
            const int pv = bp_s[s * NT + tag];
            if (s >= 1 && base + s - 1 < out_size) out[base + s - 1] = (float)pv;
            tag = pv;
        }
    }
}

// ---------------- launch ----------------
extern "C" void kernel_launch(void* const* d_in, const int* in_sizes, int n_in,
                              void* d_out, int out_size) {
    const int*   inputs = (const int*)d_in[0];
    const float* embed  = (const float*)d_in[1];
    const float* wih_f  = (const float*)d_in[2];
    const float* whh_f  = (const float*)d_in[3];
    const float* bih_f  = (const float*)d_in[4];
    const float* bhh_f  = (const float*)d_in[5];
    const float* wih_b  = (const float*)d_in[6];
    const float* whh_b  = (const float*)d_in[7];
    const float* bih_b  = (const float*)d_in[8];
    const float* bhh_b  = (const float*)d_in[9];
    const float* fc_w   = (const float*)d_in[10];
    const float* fc_b   = (const float*)d_in[11];
    const float* trans  = (const float*)d_in[12];

    cudaFuncSetAttribute(lstm_rec_kernel, cudaFuncAttributeMaxDynamicSharedMemorySize, LSTM_SMEM);

    nop_kernel<<<1, 32>>>();   // keep launch indices aligned (ncu slot)
    input_gemm_kernel<<<dim3(16, 128, 2), 256>>>(inputs, embed,
                                                 wih_f, bih_f, bhh_f,
                                                 wih_b, bih_b, bhh_b);
    nop_kernel<<<1, 32>>>();
    lstm_rec_kernel<<<128, 256, LSTM_SMEM>>>(whh_f, whh_b);
    feats_kernel<<<NS, 256>>>(fc_w, fc_b);
    viterbi_kernel<<<NB, 32>>>(trans, (float*)d_out, out_size);
}

// round 13
// speedup vs baseline: 4.4015x; 4.4015x over previous
#include <cuda_runtime.h>
#include <cstdint>
#include <math.h>

typedef unsigned long long ull;

#define NB 32
#define NS 512
#define NE 300
#define NHH 256
#define NT 12
#define NGATE 1024
#define TAG_START 10
#define TAG_STOP 11
#define FNEG (-10000.0f)

// ---------------- scratch (static device arrays; no allocation) ----------------
static __device__ float g_gates[2u * NS * NB * NGATE];   // [dir][m=s*32+b][1024]
static __device__ float g_h[2u * NS * NB * NHH];         // [dir][s][b][256]
static __device__ float g_feat[(size_t)NB * NS * NT];    // [b][s][12]
static __device__ int   g_done2[2u * NS * 8 * 32];       // h-sync: [dir][s][group] own 128B line
static __device__ int   g_gready[2 * 128 * 32];          // gate-ready: [dir][mblock] own line

__device__ __forceinline__ float sigf(float x) { return 1.f / (1.f + __expf(-x)); }

__device__ __forceinline__ ull pack2(float lo, float hi) {
    ull r; asm("mov.b64 %0, {%1, %2};" : "=l"(r) : "f"(lo), "f"(hi)); return r;
}
__device__ __forceinline__ float2 unpack2(ull v) {
    float2 f; asm("mov.b64 {%0, %1}, %2;" : "=f"(f.x), "=f"(f.y) : "l"(v)); return f;
}
__device__ __forceinline__ void ffma2(ull& d, ull a, ull b) {
    asm("fma.rn.f32x2 %0, %1, %2, %0;" : "+l"(d) : "l"(a), "l"(b));
}
__device__ __forceinline__ void red_release_add(int* p, int v) {
    asm volatile("red.release.gpu.global.add.u32 [%0], %1;" :: "l"(p), "r"(v) : "memory");
}
__device__ __forceinline__ int ld_acquire_gpu(const int* p) {
    int v; asm volatile("ld.acquire.gpu.global.b32 %0, [%1];" : "=r"(v) : "l"(p) : "memory");
    return v;
}

// ---------------- zero the counters (runs first each replay) ----------------
__global__ void zero_done_kernel() {
    const int n1 = 2 * NS * 8 * 32;
    const int n2 = 2 * 128 * 32;
    for (int i = blockIdx.x * blockDim.x + threadIdx.x; i < n1 + n2; i += gridDim.x * blockDim.x) {
        if (i < n1) g_done2[i] = 0;
        else        g_gready[i - n1] = 0;
    }
}

__global__ void nop_kernel() {}

#define LSTM_SMEM (16384 + 32768 + 36864)   // 86016 bytes

// ---------------- FUSED kernel: CTAs 0-127 = LSTM, CTAs 128-4223 = input GEMM ----------------
__global__ void __launch_bounds__(256)
fused_kernel(const int* __restrict__ inputs,
             const float* __restrict__ embed,
             const float* __restrict__ wih_f,
             const float* __restrict__ bih_f,
             const float* __restrict__ bhh_f,
             const float* __restrict__ wih_b,
             const float* __restrict__ bih_b,
             const float* __restrict__ bhh_b,
             const float* __restrict__ whh_f,
             const float* __restrict__ whh_b) {
    extern __shared__ char smraw[];
    const int bid = blockIdx.x;
    const int tid = threadIdx.x;

    if (bid >= 128) {
        // ================= GEMM branch (R6 kernel, reordered tiles, readiness publish) =====
        const int gbid = bid - 128;
        const int dir = gbid & 1;
        const int rest = gbid >> 1;
        const int nt = rest & 15;           // n fastest-varying: all 16 n-tiles of an m-block adjacent
        const int mt_raw = rest >> 4;       // 0..127
        const int mt = dir ? (127 - mt_raw) : mt_raw;   // dir1 produces high-s first
        const int n0 = nt * 64;
        const int m0 = mt * 128;
        const float* __restrict__ wih = dir ? wih_b : wih_f;
        const float* __restrict__ bih = dir ? bih_b : bih_f;
        const float* __restrict__ bhh = dir ? bhh_b : bhh_f;

        int*    tok_s = (int*)smraw;                       // 512 B
        float2* A_s   = (float2*)(smraw + 512);            // 10*128*8 = 10240
        float2* W_s   = (float2*)(smraw + 512 + 10240);    // 10*64*8  = 5120

        if (tid < 128) {
            const int m = m0 + tid;
            tok_s[tid] = inputs[(m & 31) * NS + (m >> 5)];
        }
        const int tn = tid & 15;
        const int tm = tid >> 4;

        ull acc[8][4];
#pragma unroll
        for (int i = 0; i < 8; i++)
#pragma unroll
            for (int j = 0; j < 4; j++) acc[i][j] = 0ull;

        __syncthreads();
        for (int kt = 0; kt < 15; kt++) {
            const int k0 = kt * 20;
            __syncthreads();
            for (int u = tid; u < 960; u += 256) {
                if (u < 640) {
                    const int row = u / 5, c4 = u % 5;
                    const float4 v = *(const float4*)(embed + (size_t)tok_s[row] * NE + k0 + c4 * 4);
                    A_s[(c4 * 2) * 128 + row]     = make_float2(v.x, v.y);
                    A_s[(c4 * 2 + 1) * 128 + row] = make_float2(v.z, v.w);
                } else {
                    const int idx = u - 640;
                    const int n = idx / 5, c4 = idx % 5;
                    const float4 v = *(const float4*)(wih + (size_t)(n0 + n) * NE + k0 + c4 * 4);
                    W_s[(c4 * 2) * 64 + n]     = make_float2(v.x, v.y);
                    W_s[(c4 * 2 + 1) * 64 + n] = make_float2(v.z, v.w);
                }
            }
            __syncthreads();
#pragma unroll
            for (int kp = 0; kp < 10; kp++) {
                const ulonglong2* ap = (const ulonglong2*)(A_s + kp * 128 + tm * 8);
                const ulonglong2* wp = (const ulonglong2*)(W_s + kp * 64 + tn * 4);
                const ulonglong2 a0 = ap[0], a1 = ap[1], a2 = ap[2], a3 = ap[3];
                const ulonglong2 w0 = wp[0], w1 = wp[1];
                const ull a[8] = {a0.x, a0.y, a1.x, a1.y, a2.x, a2.y, a3.x, a3.y};
                const ull w[4] = {w0.x, w0.y, w1.x, w1.y};
#pragma unroll
                for (int i = 0; i < 8; i++)
#pragma unroll
                    for (int j = 0; j < 4; j++) ffma2(acc[i][j], a[i], w[j]);
            }
        }

        const int ncol = n0 + tn * 4;
        const float4 b1 = *(const float4*)(bih + ncol);
        const float4 b2 = *(const float4*)(bhh + ncol);
        const float bx = b1.x + b2.x, by = b1.y + b2.y, bz = b1.z + b2.z, bw = b1.w + b2.w;
#pragma unroll
        for (int i = 0; i < 8; i++) {
            const int m = m0 + tm * 8 + i;
            const float2 s0 = unpack2(acc[i][0]);
            const float2 s1 = unpack2(acc[i][1]);
            const float2 s2 = unpack2(acc[i][2]);
            const float2 s3 = unpack2(acc[i][3]);
            const float4 o = make_float4(s0.x + s0.y + bx, s1.x + s1.y + by,
                                         s2.x + s2.y + bz, s3.x + s3.y + bw);
            *(float4*)(g_gates + ((size_t)dir * (NS * NB) + m) * NGATE + ncol) = o;
        }
        // publish tile completion: mblock mt of dir. 16 n-tiles must arrive.
        __threadfence();
        __syncthreads();
        if (tid == 0) red_release_add(g_gready + (dir * 128 + mt) * 32, 1);
        return;
    }

    // ================= LSTM branch (R9 kernel, plus gate-ready gating) =================
    ull*   w2_s = (ull*)smraw;                    // [kp=128][r=16] = 16KB
    float* h_s  = (float*)(smraw + 16384);        // [b=32][256] XOR-swizzled = 32KB
    ull*   p_s  = (ull*)(smraw + 49152);          // [ks=8][b=32][18] = 36KB

    const int dir = bid >> 6;
    const int cta = bid & 63;
    const int j0 = cta * 4;
    const float* __restrict__ whh = dir ? whh_b : whh_f;

    for (int idx = tid; idx < 2048; idx += 256) {
        const int kp = idx >> 4, r = idx & 15;
        const int row = (r >> 2) * NHH + j0 + (r & 3);
        const float2 wv = *(const float2*)(whh + (size_t)row * NHH + kp * 2);
        w2_s[idx] = pack2(wv.x, wv.y);
    }

    const int lane = tid & 31;
    const int ks = tid >> 5;                   // warp = k-slice
    const int b4 = lane >> 2, r4 = lane & 3;
    const int bb = tid >> 2, jj = tid & 3;     // epilogue role (tid < 128)
    const int kkL = lane & 7, bqL = lane >> 3; // staging role within warp
    const int mygrp = cta >> 3;
    float c_reg = 0.f;
    const size_t hb_dir = (size_t)dir * NS * NB * NHH;
    const int dsbase = dir * NS;
    const float* const gdir = g_gates + (size_t)dir * (NS * NB * NGATE) + j0 + jj;
    const int* const gready_dir = g_gready + dir * 128 * 32;

    // prefetch gates for t=0 (gated on GEMM readiness of that s-block)
    float n_i = 0.f, n_f = 0.f, n_g = 0.f, n_o = 0.f;
    if (tid < 128) {
        const int s0 = dir ? (NS - 1) : 0;
        if (lane == 0) {
            const int* gp = gready_dir + (s0 >> 2) * 32;
            while (ld_acquire_gpu(gp) < 16) {}
        }
        __syncwarp();
        const float* gp = gdir + ((size_t)s0 * NB + bb) * NGATE;
        n_i = __ldcg(gp); n_f = __ldcg(gp + 256); n_g = __ldcg(gp + 512); n_o = __ldcg(gp + 768);
    }
    __syncthreads();

    for (int t = 0; t < NS; t++) {
        const int s = dir ? (NS - 1 - t) : t;
        float a_i = n_i, a_f = n_f, a_g = n_g, a_o = n_o;
        if (tid < 128 && t + 1 < NS) {
            const int sn = dir ? (s - 1) : (s + 1);
            if (lane == 0) {
                const int* gp = gready_dir + (sn >> 2) * 32;
                while (ld_acquire_gpu(gp) < 16) {}
            }
            __syncwarp();
            const float* gp = gdir + ((size_t)sn * NB + bb) * NGATE;
            n_i = __ldcg(gp); n_f = __ldcg(gp + 256); n_g = __ldcg(gp + 512); n_o = __ldcg(gp + 768);
        }

        if (t > 0) {
            const int sp = dir ? (s + 1) : (s - 1);
            // hierarchical detect: 8 threads each spin on one group counter (own line)
            if (tid < 8) {
                const int* dp = g_done2 + ((dsbase + sp) * 8 + tid) * 32;
                while (ld_acquire_gpu(dp) < 8) {}
            }
            __syncthreads();
            // per-warp private slice stage: warp ks stages f in [ks*8, ks*8+8) for all b
            {
                const float4* src4 = (const float4*)(g_h + hb_dir + (size_t)sp * (NB * NHH));
                const int f = ks * 8 + kkL;
#pragma unroll
                for (int r = 0; r < 8; r++) {
                    const int b = r * 4 + bqL;
                    const float4 v = __ldcg(src4 + b * 64 + f);
                    *(float4*)(h_s + b * 256 + ((f ^ (b >> 2)) << 2)) = v;
                }
            }
            __syncwarp();

            ull acc[4][4];
#pragma unroll
            for (int bi = 0; bi < 4; bi++) {
                acc[bi][0] = 0ull; acc[bi][1] = 0ull; acc[bi][2] = 0ull; acc[bi][3] = 0ull;
            }
            const int fbase = ks * 8;
#pragma unroll
            for (int kk = 0; kk < 8; kk++) {
                const int f = fbase + kk;
                const int kp0 = f << 1;
                const ulonglong2 wa = *(const ulonglong2*)(w2_s + kp0 * 16 + r4 * 4);
                const ulonglong2 wb = *(const ulonglong2*)(w2_s + kp0 * 16 + r4 * 4 + 2);
                const ulonglong2 wc = *(const ulonglong2*)(w2_s + (kp0 + 1) * 16 + r4 * 4);
                const ulonglong2 wd = *(const ulonglong2*)(w2_s + (kp0 + 1) * 16 + r4 * 4 + 2);
#pragma unroll
                for (int bi = 0; bi < 4; bi++) {
                    const int b = b4 * 4 + bi;
                    const float4 hf = *(const float4*)(h_s + b * 256 + ((f ^ b4) << 2));
                    const ull hx = pack2(hf.x, hf.y);
                    const ull hy = pack2(hf.z, hf.w);
                    ffma2(acc[bi][0], hx, wa.x);
                    ffma2(acc[bi][1], hx, wa.y);
                    ffma2(acc[bi][2], hx, wb.x);
                    ffma2(acc[bi][3], hx, wb.y);
                    ffma2(acc[bi][0], hy, wc.x);
                    ffma2(acc[bi][1], hy, wc.y);
                    ffma2(acc[bi][2], hy, wd.x);
                    ffma2(acc[bi][3], hy, wd.y);
                }
            }
#pragma unroll
            for (int bi = 0; bi < 4; bi++) {
                ull* pp = p_s + ks * 576 + (b4 * 4 + bi) * 18 + r4 * 4;
                *(ulonglong2*)pp       = make_ulonglong2(acc[bi][0], acc[bi][1]);
                *(ulonglong2*)(pp + 2) = make_ulonglong2(acc[bi][2], acc[bi][3]);
            }
            __syncthreads();
            if (tid < 128) {
                const float2* pf = (const float2*)p_s;
#pragma unroll
                for (int q = 0; q < 8; q++) {
                    const int base = q * 576 + bb * 18 + jj;
                    const float2 v0 = pf[base + 0];
                    const float2 v1 = pf[base + 4];
                    const float2 v2 = pf[base + 8];
                    const float2 v3 = pf[base + 12];
                    a_i += v0.x + v0.y;
                    a_f += v1.x + v1.y;
                    a_g += v2.x + v2.y;
                    a_o += v3.x + v3.y;
                }
            }
        }
        if (tid < 128) {
            const float ig = sigf(a_i), fg = sigf(a_f), og = sigf(a_o);
            const float tg = 2.f * sigf(2.f * a_g) - 1.f;             // tanh
            const float cn = fg * c_reg + ig * tg;
            const float hn = og * (2.f * sigf(2.f * cn) - 1.f);
            c_reg = cn;
            __stcg(g_h + hb_dir + ((size_t)s * NB + bb) * NHH + j0 + jj, hn);
        }
        __syncthreads();
        if (tid == 0)
            red_release_add(g_done2 + ((dsbase + s) * 8 + mygrp) * 32, 1);
    }
}

// ---------------- Phase C1: feats = hs @ fc_w^T + fc_b ----------------
__global__ void feats_kernel(const float* __restrict__ fc_w,
                             const float* __restrict__ fc_b) {
    __shared__ float fcw_s[NT * 512];
    __shared__ float fcb_s[NT];
    const int s = blockIdx.x;
    const int tid = threadIdx.x;
    for (int i = tid; i < NT * 512; i += 256) fcw_s[i] = fc_w[i];
    if (tid < NT) fcb_s[tid] = fc_b[tid];
    __syncthreads();

    const int w = tid >> 5, lane = tid & 31;
#pragma unroll
    for (int rep = 0; rep < 4; rep++) {
        const int b = w + rep * 8;
        const float4* hf = (const float4*)(g_h + ((size_t)s * NB + b) * NHH);
        const float4* hb = (const float4*)(g_h + (size_t)NS * NB * NHH + ((size_t)s * NB + b) * NHH);
        const float4 v0 = __ldcg(hf + lane);
        const float4 v1 = __ldcg(hf + lane + 32);
        const float4 v2 = __ldcg(hb + lane);
        const float4 v3 = __ldcg(hb + lane + 32);
#pragma unroll
        for (int tt = 0; tt < NT; tt++) {
            const float4* wr = (const float4*)(fcw_s + tt * 512);
            const float4 w0 = wr[lane];
            const float4 w1 = wr[lane + 32];
            const float4 w2 = wr[lane + 64];
            const float4 w3 = wr[lane + 96];
            float p = v0.x * w0.x + v0.y * w0.y + v0.z * w0.z + v0.w * w0.w
                    + v1.x * w1.x + v1.y * w1.y + v1.z * w1.z + v1.w * w1.w
                    + v2.x * w2.x + v2.y * w2.y + v2.z * w2.z + v2.w * w2.w
                    + v3.x * w3.x + v3.y * w3.y + v3.z * w3.z + v3.w * w3.w;
            p += __shfl_xor_sync(0xffffffffu, p, 16);
            p += __shfl_xor_sync(0xffffffffu, p, 8);
            p += __shfl_xor_sync(0xffffffffu, p, 4);
            p += __shfl_xor_sync(0xffffffffu, p, 2);
            p += __shfl_xor_sync(0xffffffffu, p, 1);
            if (lane == 0) g_feat[((size_t)b * NS + s) * NT + tt] = p + fcb_s[tt];
        }
    }
}

// ---------------- Phase C2: Viterbi, one warp per batch ----------------
__global__ void viterbi_kernel(const float* __restrict__ trans,
                               float* __restrict__ out, int out_size) {
    __shared__ float feat_s[NS * NT];
    __shared__ unsigned char bp_s[NS * NT];
    __shared__ float term_s[NT];
    const int b = blockIdx.x;
    const int lane = threadIdx.x;  // 32

    const float4* src = (const float4*)(g_feat + (size_t)b * NS * NT);
    float4* dst = (float4*)feat_s;
    for (int i = lane; i < (NS * NT) / 4; i += 32) dst[i] = __ldcg(src + i);

    const int tl = (lane < NT) ? lane : (NT - 1);
    float tr_reg[NT];
#pragma unroll
    for (int p = 0; p < NT; p++) tr_reg[p] = trans[p * NT + tl];
    const float tr_stop = trans[tl * NT + TAG_STOP];
    __syncwarp();

    float v = (lane == TAG_START) ? 0.f : FNEG;
    for (int s = 0; s < NS; s++) {
        float best = -3.0e38f;
        int bpi = 0;
#pragma unroll
        for (int p = 0; p < NT; p++) {
            const float sc = __shfl_sync(0xffffffffu, v, p) + tr_reg[p];
            if (sc > best) { best = sc; bpi = p; }
        }
        v = best + feat_s[s * NT + tl];
        if (lane < NT) bp_s[s * NT + lane] = (unsigned char)bpi;
    }
    if (lane < NT) term_s[lane] = v + tr_stop;
    __syncwarp();
    if (lane == 0) {
        float best = term_s[0];
        int last = 0;
#pragma unroll
        for (int tt = 1; tt < NT; tt++)
            if (term_s[tt] > best) { best = term_s[tt]; last = tt; }
        if (b < out_size) out[b] = best;
        const int base = NB + b * NS;
        if (base + NS - 1 < out_size) out[base + NS - 1] = (float)last;
        int tag = last;
        for (int s = NS - 1; s >= 0; s--) {
            const int pv = bp_s[s * NT + tag];
            if (s >= 1 && base + s - 1 < out_size) out[base + s - 1] = (float)pv;
            tag = pv;
        }
    }
}

// ---------------- launch ----------------
extern "C" void kernel_launch(void* const* d_in, const int* in_sizes, int n_in,
                              void* d_out, int out_size) {
    const int*   inputs = (const int*)d_in[0];
    const float* embed  = (const float*)d_in[1];
    const float* wih_f  = (const float*)d_in[2];
    const float* whh_f  = (const float*)d_in[3];
    const float* bih_f  = (const float*)d_in[4];
    const float* bhh_f  = (const float*)d_in[5];
    const float* wih_b  = (const float*)d_in[6];
    const float* whh_b  = (const float*)d_in[7];
    const float* bih_b  = (const float*)d_in[8];
    const float* bhh_b  = (const float*)d_in[9];
    const float* fc_w   = (const float*)d_in[10];
    const float* fc_b   = (const float*)d_in[11];
    const float* trans  = (const float*)d_in[12];

    cudaFuncSetAttribute(fused_kernel, cudaFuncAttributeMaxDynamicSharedMemorySize, LSTM_SMEM);

    zero_done_kernel<<<256, 256>>>();
    nop_kernel<<<1, 32>>>();
    nop_kernel<<<1, 32>>>();   // keep the ncu capture slot aligned on the fused kernel
    fused_kernel<<<128 + 4096, 256, LSTM_SMEM>>>(inputs, embed,
                                                 wih_f, bih_f, bhh_f,
                                                 wih_b, bih_b, bhh_b,
                                                 whh_f, whh_b);
    feats_kernel<<<NS, 256>>>(fc_w, fc_b);
    viterbi_kernel<<<NB, 32>>>(trans, (float*)d_out, out_size);
}